// round 16
// baseline (speedup 1.0000x reference)
#include <cuda_runtime.h>
#include <cuda_bf16.h>
#include <cuda_fp16.h>
#include <math.h>
#include <cstdint>

// Problem constants
#define Bb   64
#define Cc   64
#define Ll   8192
#define Ff   4097          // rfft bins
#define NFFT 4096          // complex FFT size (L/2)
#define HID  128
#define TILE_F  64
#define NTILES  65         // 65*64 = 4160 >= 4097
#define SEG     13
#define TPS     5          // tiles per segment (13*5 = 65)

// ---------------- scratch (device globals; no allocations allowed) ----------
__device__ __half g_fxre[Bb * Cc * Ff];         // 33.5 MB rfft real (ortho, fp16)
__device__ __half g_fxim[Bb * Cc * Ff];         // 33.5 MB rfft imag (ortho, fp16)
__device__ float g_Spart[SEG * 2 * Bb * HID];   // per-segment SELU sums
__device__ float g_edge[2 * Bb * HID * 2];      // y[h,0], y[h,F-1]
__device__ float g_C[2 * Bb * 3];               // softmax coefficients C_R, C_I

// ---------------- helpers ----------------------------------------------------
__device__ __forceinline__ uint32_t smem_u32(const void* p) {
    uint32_t a;
    asm("{ .reg .u64 t; cvta.to.shared.u64 t, %1; cvt.u32.u64 %0, t; }" : "=r"(a) : "l"(p));
    return a;
}
__device__ __forceinline__ void sts32(uint32_t addr, uint32_t v) {
    asm volatile("st.shared.b32 [%0], %1;" :: "r"(addr), "r"(v) : "memory");
}
__device__ __forceinline__ void ldsm4(uint32_t addr, uint32_t* r) {
    asm volatile("ldmatrix.sync.aligned.m8n8.x4.shared.b16 {%0,%1,%2,%3}, [%4];"
                 : "=r"(r[0]), "=r"(r[1]), "=r"(r[2]), "=r"(r[3]) : "r"(addr));
}
__device__ __forceinline__ void mma16816(float* c, const uint32_t* a, uint32_t b0, uint32_t b1) {
    asm volatile("mma.sync.aligned.m16n8k16.row.col.f32.f16.f16.f32 "
                 "{%0,%1,%2,%3}, {%4,%5,%6,%7}, {%8,%9}, {%0,%1,%2,%3};"
                 : "+f"(c[0]), "+f"(c[1]), "+f"(c[2]), "+f"(c[3])
                 : "r"(a[0]), "r"(a[1]), "r"(a[2]), "r"(a[3]), "r"(b0), "r"(b1));
}
__device__ __forceinline__ float2 cmul(float2 a, float2 b) {
    return make_float2(a.x * b.x - a.y * b.y, a.x * b.y + a.y * b.x);
}
__device__ __forceinline__ int fpad(int i) { return i + (i >> 4); }

// ---------------- 4/8-point DFT in registers ---------------------------------
__device__ __forceinline__ void dft4(float2 a, float2 b, float2 c, float2 d,
                                     float sgn, float2* o) {
    float t0r = a.x + c.x, t0i = a.y + c.y;
    float t1r = a.x - c.x, t1i = a.y - c.y;
    float t2r = b.x + d.x, t2i = b.y + d.y;
    float t3r = -sgn * (b.y - d.y), t3i = sgn * (b.x - d.x);
    o[0] = make_float2(t0r + t2r, t0i + t2i);
    o[1] = make_float2(t1r + t3r, t1i + t3i);
    o[2] = make_float2(t0r - t2r, t0i - t2i);
    o[3] = make_float2(t1r - t3r, t1i - t3i);
}
__device__ __forceinline__ void dft8(float2* x, float sgn) {
    const float Rq = 0.7071067811865476f;
    float2 E[4], O[4];
    dft4(x[0], x[2], x[4], x[6], sgn, E);
    dft4(x[1], x[3], x[5], x[7], sgn, O);
    float2 w1 = make_float2(Rq, sgn * Rq);
    float2 w2 = make_float2(0.f, sgn);
    float2 w3 = make_float2(-Rq, sgn * Rq);
    O[1] = cmul(O[1], w1);
    O[2] = cmul(O[2], w2);
    O[3] = cmul(O[3], w3);
#pragma unroll
    for (int k = 0; k < 4; k++) {
        x[k]     = make_float2(E[k].x + O[k].x, E[k].y + O[k].y);
        x[k + 4] = make_float2(E[k].x - O[k].x, E[k].y - O[k].y);
    }
}

// apply stage twiddles W^p..W^7p (p = tid >> sh scaled) to both rows
__device__ __forceinline__ void twiddle_x2(float2* x, float2* y, int tid, int sh, float sgn) {
    int   p  = tid >> sh;
    float th = sgn * 0.0015339807878856412f * (float)(p << sh);  // 2π/4096
    float c1v, s1v;
    __sincosf(th, &s1v, &c1v);
    float2 W1 = make_float2(c1v, s1v);
    float2 W2 = cmul(W1, W1);
    float2 W3 = cmul(W2, W1);
    float2 W4 = cmul(W2, W2);
    float2 W5 = cmul(W3, W2);
    float2 W6 = cmul(W3, W3);
    float2 W7 = cmul(W4, W3);
    x[1] = cmul(x[1], W1); x[2] = cmul(x[2], W2); x[3] = cmul(x[3], W3);
    x[4] = cmul(x[4], W4); x[5] = cmul(x[5], W5); x[6] = cmul(x[6], W6);
    x[7] = cmul(x[7], W7);
    y[1] = cmul(y[1], W1); y[2] = cmul(y[2], W2); y[3] = cmul(y[3], W3);
    y[4] = cmul(y[4], W4); y[5] = cmul(y[5], W5); y[6] = cmul(y[6], W6);
    y[7] = cmul(y[7], W7);
}

// one generic smem->smem Stockham stage (both rows); t in [0,3]
__device__ __forceinline__ void fft_stage_smem(float2* A, float2* B, int tid,
                                               float sgn, int t) {
    int sh = 3 * t;
    int s  = 1 << sh;
    float2 x[8], y[8];
#pragma unroll
    for (int j = 0; j < 8; j++) {
        int ii = fpad(tid + (j << 9));
        x[j] = A[ii];
        y[j] = B[ii];
    }
    __syncthreads();
    dft8(x, sgn);
    dft8(y, sgn);
    if (t < 3) twiddle_x2(x, y, tid, sh, sgn);
    int q    = tid & (s - 1);
    int base = q + ((tid >> sh) << (sh + 3));
#pragma unroll
    for (int k = 0; k < 8; k++) {
        int oo = fpad(base + (k << sh));
        A[oo] = x[k];
        B[oo] = y[k];
    }
    __syncthreads();
}

#define ROW_PAD   4352                              // 4096 + 256 float2
#define FFT_SMEM2 (2 * ROW_PAD * (int)sizeof(float2))  // 69632 B
#define FFT_T     512

// ---------------- K1: forward rfft (ortho), 2 rows per CTA -------------------
__global__ void __launch_bounds__(FFT_T, 2) k_fwd(const float* __restrict__ xg) {
    extern __shared__ float2 smc[];
    float2* A = smc;
    float2* B = smc + ROW_PAD;
    int row0 = blockIdx.x * 2;
    int row1 = row0 + 1;
    int tid  = threadIdx.x;

    const float2* xin0 = (const float2*)(xg + (size_t)row0 * Ll);
    const float2* xin1 = (const float2*)(xg + (size_t)row1 * Ll);

    // stage 0: global -> registers -> smem (no staging pass)
    {
        float2 x[8], y[8];
#pragma unroll
        for (int j = 0; j < 8; j++) {
            int m = tid + (j << 9);
            x[j] = xin0[m];                  // (even, odd) packed complex
            y[j] = xin1[m];
        }
        dft8(x, -1.0f);
        dft8(y, -1.0f);
        twiddle_x2(x, y, tid, 0, -1.0f);
        int base = tid << 3;
#pragma unroll
        for (int k = 0; k < 8; k++) {
            int oo = fpad(base + k);
            A[oo] = x[k];
            B[oo] = y[k];
        }
        __syncthreads();
    }
    fft_stage_smem(A, B, tid, -1.0f, 1);
    fft_stage_smem(A, B, tid, -1.0f, 2);
    // stage 3: thread-local slots (read/write same indices), no twiddle
    {
        float2 x[8], y[8];
#pragma unroll
        for (int j = 0; j < 8; j++) {
            int ii = fpad(tid + (j << 9));
            x[j] = A[ii];
            y[j] = B[ii];
        }
        dft8(x, -1.0f);
        dft8(y, -1.0f);
#pragma unroll
        for (int k = 0; k < 8; k++) {
            int oo = fpad(tid + (k << 9));
            A[oo] = x[k];
            B[oo] = y[k];
        }
        __syncthreads();
    }

    // Hermitian unpack, paired: X[k] = E + U, X[N-k] = conj(E - U), U = W^k O
    const float sc = 0.011048543456039804f;  // 1/sqrt(8192)
    __half* outre0 = g_fxre + (size_t)row0 * Ff;
    __half* outim0 = g_fxim + (size_t)row0 * Ff;
    __half* outre1 = g_fxre + (size_t)row1 * Ff;
    __half* outim1 = g_fxim + (size_t)row1 * Ff;
#pragma unroll 1
    for (int i = 0; i < 4; i++) {
        int k = tid + (i << 9);              // [0, 2048)
        if (k == 0) {
#pragma unroll
            for (int r = 0; r < 2; r++) {
                float2* T   = r ? B : A;
                __half* ore = r ? outre1 : outre0;
                __half* oim = r ? outim1 : outim0;
                float2 z0 = T[fpad(0)];
                ore[0]    = __float2half((z0.x + z0.y) * sc);  oim[0]    = __float2half(0.f);
                ore[4096] = __float2half((z0.x - z0.y) * sc);  oim[4096] = __float2half(0.f);
                float2 zc = T[fpad(2048)];
                ore[2048] = __float2half(zc.x * sc);           oim[2048] = __float2half(-zc.y * sc);
            }
        } else {
            int   m = 4096 - k;
            int   pk = fpad(k), pm = fpad(m);
            float cw, sw;
            __sincosf((float)k * (3.14159265358979324f / 4096.0f), &sw, &cw);
#pragma unroll
            for (int r = 0; r < 2; r++) {
                float2* T   = r ? B : A;
                __half* ore = r ? outre1 : outre0;
                __half* oim = r ? outim1 : outim0;
                float2 zk = T[pk], zm = T[pm];
                float Er = 0.5f * (zk.x + zm.x), Ei = 0.5f * (zk.y - zm.y);
                float Or = 0.5f * (zk.y + zm.y), Oi = 0.5f * (zm.x - zk.x);
                float Ur = cw * Or + sw * Oi;
                float Ui = cw * Oi - sw * Or;
                ore[k] = __float2half((Er + Ur) * sc);  oim[k] = __float2half((Ei + Ui) * sc);
                ore[m] = __float2half((Er - Ur) * sc);  oim[m] = __float2half((Ui - Ei) * sc);
            }
        }
    }
}

// ---------------- K2a: conv1 via mma.sync f16 + SELU + f-sum -----------------
#define A_TAP_BYTES 16384
#define B_BYTES     8448          // 66 * 128
__global__ void __launch_bounds__(256, 3) k_conv(const float* __restrict__ w1R,
                                                 const float* __restrict__ b1R,
                                                 const float* __restrict__ w1I,
                                                 const float* __restrict__ b1I) {
    extern __shared__ __align__(1024) char dynsm[];
    __shared__ float s_red[2][128];

    int seg  = blockIdx.x;
    int b    = blockIdx.y;
    int path = blockIdx.z;
    const __half* in = (path == 0) ? g_fxre : g_fxim;
    const float* w1 = (path == 0) ? w1R : w1I;
    const float* b1 = (path == 0) ? b1R : b1I;

    int tid  = threadIdx.x;
    int wid  = tid >> 5;
    int lane = tid & 31;
    int wm   = wid & 3;            // M group (32 rows)
    int wn   = wid >> 2;           // N group (32 cols)

    int t_beg = seg * TPS;
    int t_end = t_beg + TPS;       // 13*5 = 65 exactly

    uint32_t A0 = smem_u32(dynsm);
    uint32_t B0 = A0 + 3 * A_TAP_BYTES;

    // ---- weights -> f16 smem (one-time, float2 loads) ----
    for (int idx = tid; idx < 128 * 32; idx += 256) {
        int h  = idx >> 5;
        int cp = idx & 31;
        const float2* wp = (const float2*)(w1 + ((size_t)(h * 64 + 2 * cp)) * 3);
        float2 v01 = wp[0];
        float2 v23 = wp[1];
        float2 v45 = wp[2];
        uint32_t off = (uint32_t)h * 128 + (((uint32_t)cp * 4) ^ (((uint32_t)h & 7) << 4));
        __half2 t0 = __floats2half2_rn(v01.x, v23.y);
        __half2 t1 = __floats2half2_rn(v01.y, v45.x);
        __half2 t2 = __floats2half2_rn(v23.x, v45.y);
        sts32(A0 + 0 * A_TAP_BYTES + off, *(uint32_t*)&t0);
        sts32(A0 + 1 * A_TAP_BYTES + off, *(uint32_t*)&t1);
        sts32(A0 + 2 * A_TAP_BYTES + off, *(uint32_t*)&t2);
    }

    float bias[2][2];
#pragma unroll
    for (int mi = 0; mi < 2; mi++)
#pragma unroll
        for (int hf = 0; hf < 2; hf++)
            bias[mi][hf] = b1[wm * 32 + mi * 16 + (lane >> 2) + hf * 8];

    // B loader: thread -> (cp = tid>>3, jslot = tid&7), 9 j-iterations
    int cp = tid >> 3;
    int js = tid & 7;
    const __half* r0g = in + (size_t)(b * 64 + 2 * cp) * Ff;
    const __half* r1g = r0g + Ff;
    uint32_t brot = ((uint32_t)js << 4);

    uint32_t xv[9];
    auto fetchB = [&](int t) {
        int f0 = t * TILE_F;
#pragma unroll
        for (int i = 0; i < 9; i++) {
            int j = js + 8 * i;
            __half2 tv = __floats2half2_rn(0.f, 0.f);
            if (j < 66) {
                int f = f0 - 1 + j;
                if (f >= 0 && f <= 4096) tv = __halves2half2(r0g[f], r1g[f]);
            }
            xv[i] = *(uint32_t*)&tv;
        }
    };
    auto storeB = [&](uint32_t Bbuf) {
#pragma unroll
        for (int i = 0; i < 9; i++) {
            int j = js + 8 * i;
            if (j < 66)
                sts32(Bbuf + (uint32_t)j * 128 + (((uint32_t)cp * 4) ^ brot), xv[i]);
        }
    };

    float s[2][2] = {{0.f, 0.f}, {0.f, 0.f}};
    const float SC = 1.0507009873554805f;
    const float SA = 1.7580993408473766f;    // SC * AL

    // lane pieces for ldmatrix addressing
    uint32_t lrow_off = (uint32_t)((lane & 7) + (lane & 8));      // A frag rows
    uint32_t kbyte_hi = (lane & 16) ? 16u : 0u;                   // A k-half
    uint32_t b_row_l  = (uint32_t)(wn * 32 + (lane & 7) + ((lane & 16) ? 8 : 0)); // B rows
    uint32_t b_khalf  = (lane & 8) ? 16u : 0u;                    // B k-half

    fetchB(t_beg);
    storeB(B0 + (uint32_t)(t_beg & 1) * B_BYTES);
    __syncthreads();

#pragma unroll 1
    for (int t = t_beg; t < t_end; t++) {
        if (t + 1 < t_end) fetchB(t + 1);    // prefetch into regs

        uint32_t Bbuf = B0 + (uint32_t)(t & 1) * B_BYTES;
        float acc[2][4][4];
#pragma unroll
        for (int mi = 0; mi < 2; mi++)
#pragma unroll
            for (int ni = 0; ni < 4; ni++)
#pragma unroll
                for (int e = 0; e < 4; e++) acc[mi][ni][e] = 0.f;

#pragma unroll
        for (int tap = 0; tap < 3; tap++) {
            uint32_t Atap = A0 + (uint32_t)tap * A_TAP_BYTES;
#pragma unroll
            for (int kf = 0; kf < 4; kf++) {
                uint32_t a[2][4];
#pragma unroll
                for (int mi = 0; mi < 2; mi++) {
                    uint32_t row  = (uint32_t)(wm * 32 + mi * 16) + lrow_off;
                    uint32_t kb   = (uint32_t)kf * 32 + kbyte_hi;
                    uint32_t addr = Atap + row * 128 + (kb ^ ((row & 7) << 4));
                    ldsm4(addr, a[mi]);
                }
                uint32_t bb[4][2];
                uint32_t kbB = (uint32_t)kf * 32 + b_khalf;
#pragma unroll
                for (int np = 0; np < 2; np++) {
                    uint32_t r    = b_row_l + (uint32_t)(np * 16 + tap);
                    uint32_t addr = Bbuf + r * 128 + (kbB ^ ((r & 7) << 4));
                    uint32_t rg[4];
                    ldsm4(addr, rg);
                    bb[np * 2][0]     = rg[0];
                    bb[np * 2][1]     = rg[1];
                    bb[np * 2 + 1][0] = rg[2];
                    bb[np * 2 + 1][1] = rg[3];
                }
#pragma unroll
                for (int mi = 0; mi < 2; mi++)
#pragma unroll
                    for (int ni = 0; ni < 4; ni++)
                        mma16816(acc[mi][ni], a[mi], bb[ni][0], bb[ni][1]);
            }
        }

        // epilogue: bias + SELU + row sums (+ edges only in boundary tiles)
        if (t != 0 && t != NTILES - 1) {
#pragma unroll
            for (int mi = 0; mi < 2; mi++)
#pragma unroll
                for (int ni = 0; ni < 4; ni++)
#pragma unroll
                    for (int e = 0; e < 4; e++) {
                        int   hf = e >> 1;
                        float v  = acc[mi][ni][e] + bias[mi][hf];
                        float y  = (v > 0.f) ? SC * v : SA * (__expf(v) - 1.f);
                        s[mi][hf] += y;
                    }
        } else {
            int f0 = t * TILE_F;
#pragma unroll
            for (int mi = 0; mi < 2; mi++)
#pragma unroll
                for (int ni = 0; ni < 4; ni++)
#pragma unroll
                    for (int e = 0; e < 4; e++) {
                        int f = f0 + wn * 32 + ni * 8 + (lane & 3) * 2 + (e & 1);
                        if (f <= 4096) {
                            int   hf = e >> 1;
                            float v  = acc[mi][ni][e] + bias[mi][hf];
                            float y  = (v > 0.f) ? SC * v : SA * (__expf(v) - 1.f);
                            s[mi][hf] += y;
                            if (f == 0 || f == 4096) {
                                int    h  = wm * 32 + mi * 16 + (lane >> 2) + hf * 8;
                                size_t eb = (((size_t)path * 64 + b) * 128 + h) * 2;
                                g_edge[eb + ((f == 0) ? 0 : 1)] = y;
                            }
                        }
                    }
        }

        if (t + 1 < t_end) storeB(B0 + (uint32_t)((t + 1) & 1) * B_BYTES);
        __syncthreads();
    }

    // cross-lane reduce (cols live on lane%4 quads)
#pragma unroll
    for (int mi = 0; mi < 2; mi++)
#pragma unroll
        for (int hf = 0; hf < 2; hf++) {
            float v = s[mi][hf];
            v += __shfl_xor_sync(0xffffffffu, v, 1);
            v += __shfl_xor_sync(0xffffffffu, v, 2);
            s[mi][hf] = v;
        }
    if ((lane & 3) == 0) {
#pragma unroll
        for (int mi = 0; mi < 2; mi++)
#pragma unroll
            for (int hf = 0; hf < 2; hf++) {
                int h = wm * 32 + mi * 16 + (lane >> 2) + hf * 8;
                s_red[wn][h] = s[mi][hf];
            }
    }
    __syncthreads();
    if (tid < 128) {
        float S = s_red[0][tid] + s_red[1][tid];
        g_Spart[(((size_t)seg * 2 + path) * 64 + b) * 128 + tid] = S;
    }
}

// ---------------- K2b: pooled conv2 + softmax --------------------------------
__global__ void __launch_bounds__(128) k_pool(const float* __restrict__ w2R,
                                              const float* __restrict__ b2R,
                                              const float* __restrict__ w2I,
                                              const float* __restrict__ b2I) {
    int bx   = blockIdx.x;
    int path = bx >> 6;
    int b    = bx & 63;
    const float* w2 = path ? w2I : w2R;
    const float* b2 = path ? b2I : b2R;
    int h = threadIdx.x;

    size_t base = ((size_t)path * 64 + b) * 128 + h;
    float  S    = 0.f;
#pragma unroll
    for (int sg = 0; sg < SEG; sg++)
        S += g_Spart[(((size_t)sg * 2 + path) * 64 + b) * 128 + h];
    float y0 = g_edge[base * 2 + 0];
    float yl = g_edge[base * 2 + 1];

    __shared__ float red[3][128];
#pragma unroll
    for (int n = 0; n < 3; n++) {
        const float* wp = w2 + ((size_t)n * 128 + h) * 3;
        red[n][h] = wp[0] * (S - yl) + wp[1] * S + wp[2] * (S - y0);
    }
    __syncthreads();
    for (int off = 64; off >= 1; off >>= 1) {
        if (h < off) {
#pragma unroll
            for (int n = 0; n < 3; n++) red[n][h] += red[n][h + off];
        }
        __syncthreads();
    }
    if (h == 0) {
        float z0 = red[0][0] / (float)Ff + b2[0];
        float z1 = red[1][0] / (float)Ff + b2[1];
        float z2 = red[2][0] / (float)Ff + b2[2];
        float m  = fmaxf(z0, fmaxf(z1, z2));
        float e0 = expf(z0 - m), e1 = expf(z1 - m), e2 = expf(z2 - m);
        float inv = 1.f / (e0 + e1 + e2);
        size_t cb = ((size_t)path * 64 + b) * 3;
        g_C[cb + 0] = e0 * inv;
        g_C[cb + 1] = e1 * inv;
        g_C[cb + 2] = e2 * inv;
    }
}

// ---------------- K3: fused Kf-multiply + inverse pack + irfft, 2 rows -------
__global__ void __launch_bounds__(FFT_T, 2) k_inv(const float* __restrict__ param,
                                                  float* __restrict__ out) {
    extern __shared__ float2 smc[];
    float2* A = smc;
    float2* B = smc + ROW_PAD;

    int row0 = blockIdx.x * 2;
    int row1 = row0 + 1;
    int b    = row0 >> 6;                    // same b for both rows
    int c0   = row0 & 63;
    int tid  = threadIdx.x;

    float cr0 = g_C[((size_t)0 * 64 + b) * 3 + 0];
    float cr1 = g_C[((size_t)0 * 64 + b) * 3 + 1];
    float cr2 = g_C[((size_t)0 * 64 + b) * 3 + 2];
    float ci0 = g_C[((size_t)1 * 64 + b) * 3 + 0];
    float ci1 = g_C[((size_t)1 * 64 + b) * 3 + 1];
    float ci2 = g_C[((size_t)1 * 64 + b) * 3 + 2];

    const __half* fre0 = g_fxre + (size_t)row0 * Ff;
    const __half* fim0 = g_fxim + (size_t)row0 * Ff;
    const __half* fre1 = g_fxre + (size_t)row1 * Ff;
    const __half* fim1 = g_fxim + (size_t)row1 * Ff;

    // spectral multiply at one bin f for row-channel cc; returns Y = fx * Kf
    auto specmul = [&](int f, int cc, const __half* fre, const __half* fim) {
        float2 w0 = *(const float2*)(param + (((size_t)0 * 64 + cc) * Ff + f) * 2);
        float2 w1 = *(const float2*)(param + (((size_t)1 * 64 + cc) * Ff + f) * 2);
        float2 w2 = *(const float2*)(param + (((size_t)2 * 64 + cc) * Ff + f) * 2);
        float KfR = cr0 * w0.x + cr1 * w1.x + cr2 * w2.x;
        float KfI = ci0 * w0.y + ci1 * w1.y + ci2 * w2.y;
        float fr = __half2float(fre[f]), fi = __half2float(fim[f]);
        return make_float2(fr * KfR - fi * KfI, fr * KfI + fi * KfR);
    };

    // fused: Y = fx*Kf and inverse pack Z[k] = E + iO, written to smem once
#pragma unroll 1
    for (int i = 0; i < 4; i++) {
        int k = tid + (i << 9);              // [0, 2048)
        if (k == 0) {
#pragma unroll
            for (int r = 0; r < 2; r++) {
                int cc = c0 + r;
                const __half* fre = r ? fre1 : fre0;
                const __half* fim = r ? fim1 : fim0;
                float2* T = r ? B : A;
                float2 Y0 = specmul(0, cc, fre, fim);     // imag discarded (C2R)
                float2 Yn = specmul(4096, cc, fre, fim);  // Nyquist, imag discarded
                float Er = 0.5f * (Y0.x + Yn.x);
                float Dr = 0.5f * (Y0.x - Yn.x);
                T[fpad(0)] = make_float2(Er, Dr);
                float2 Yc = specmul(2048, cc, fre, fim);  // self-paired bin
                T[fpad(2048)] = make_float2(Yc.x, -Yc.y);
            }
        } else {
            int   m  = 4096 - k;
            int   pk = fpad(k), pm = fpad(m);
            float cw, sw;
            __sincosf((float)k * (3.14159265358979324f / 4096.0f), &sw, &cw);
#pragma unroll
            for (int r = 0; r < 2; r++) {
                int cc = c0 + r;
                const __half* fre = r ? fre1 : fre0;
                const __half* fim = r ? fim1 : fim0;
                float2* T = r ? B : A;
                float2 Yk = specmul(k, cc, fre, fim);
                float2 Ym = specmul(m, cc, fre, fim);
                float Er = 0.5f * (Yk.x + Ym.x), Ei = 0.5f * (Yk.y - Ym.y);
                float Dr = 0.5f * (Yk.x - Ym.x), Di = 0.5f * (Yk.y + Ym.y);
                float Or = Dr * cw - Di * sw;
                float Oi = Dr * sw + Di * cw;
                T[pk] = make_float2(Er - Oi, Ei + Or);
                T[pm] = make_float2(Er + Oi, Or - Ei);
            }
        }
    }
    __syncthreads();

    fft_stage_smem(A, B, tid, +1.0f, 0);
    fft_stage_smem(A, B, tid, +1.0f, 1);
    fft_stage_smem(A, B, tid, +1.0f, 2);

    // stage 3: butterfly in registers, scaled write DIRECTLY to global
    const float sc = 0.022097086912079608f;  // sqrt(8192) / 4096
    float2* o0 = (float2*)(out + (size_t)row0 * Ll);
    float2* o1 = (float2*)(out + (size_t)row1 * Ll);
    {
        float2 x[8], y[8];
#pragma unroll
        for (int j = 0; j < 8; j++) {
            int ii = fpad(tid + (j << 9));
            x[j] = A[ii];
            y[j] = B[ii];
        }
        dft8(x, +1.0f);
        dft8(y, +1.0f);
#pragma unroll
        for (int k = 0; k < 8; k++) {
            int m = tid + (k << 9);
            o0[m] = make_float2(x[k].x * sc, x[k].y * sc);
            o1[m] = make_float2(y[k].x * sc, y[k].y * sc);
        }
    }
}

// ---------------- launch -----------------------------------------------------
extern "C" void kernel_launch(void* const* d_in, const int* in_sizes, int n_in,
                              void* d_out, int out_size) {
    const float* x   = (const float*)d_in[0];
    const float* par = (const float*)d_in[1];
    const float* wR1 = (const float*)d_in[2];
    const float* bR1 = (const float*)d_in[3];
    const float* wR2 = (const float*)d_in[4];
    const float* bR2 = (const float*)d_in[5];
    const float* wI1 = (const float*)d_in[6];
    const float* bI1 = (const float*)d_in[7];
    const float* wI2 = (const float*)d_in[8];
    const float* bI2 = (const float*)d_in[9];
    float* out = (float*)d_out;

    const int convSmem = 3 * A_TAP_BYTES + 2 * B_BYTES;  // 66048
    cudaFuncSetAttribute(k_conv, cudaFuncAttributeMaxDynamicSharedMemorySize, convSmem);
    cudaFuncSetAttribute(k_fwd,  cudaFuncAttributeMaxDynamicSharedMemorySize, FFT_SMEM2);
    cudaFuncSetAttribute(k_inv,  cudaFuncAttributeMaxDynamicSharedMemorySize, FFT_SMEM2);

    k_fwd<<<Bb * Cc / 2, FFT_T, FFT_SMEM2>>>(x);
    dim3 gconv(SEG, Bb, 2);
    k_conv<<<gconv, 256, convSmem>>>(wR1, bR1, wI1, bI1);
    k_pool<<<2 * Bb, 128>>>(wR2, bR2, wI2, bI2);
    k_inv<<<Bb * Cc / 2, FFT_T, FFT_SMEM2>>>(par, out);
}

// round 17
// speedup vs baseline: 1.4773x; 1.4773x over previous
#include <cuda_runtime.h>
#include <cuda_bf16.h>
#include <math.h>
#include <cstdint>

// Problem constants
#define Bb   64
#define Cc   64
#define Ll   8192
#define Ff   4097          // rfft bins
#define NFFT 4096          // complex FFT size (L/2)
#define HID  128
#define TILE_F  64
#define NTILES  65         // 65*64 = 4160 >= 4097
#define SEG     13
#define TPS     5          // tiles per segment (13*5 = 65)

// ---------------- scratch (device globals; no allocations allowed) ----------
__device__ float g_fxre[Bb * Cc * Ff];          // 67 MB  rfft real (ortho)
__device__ float g_fxim[Bb * Cc * Ff];          // 67 MB  rfft imag (ortho)
__device__ float g_Spart[SEG * 2 * Bb * HID];   // per-segment SELU sums
__device__ float g_edge[2 * Bb * HID * 2];      // y[h,0], y[h,F-1]
__device__ float g_C[2 * Bb * 3];               // softmax coefficients C_R, C_I

// ---------------- helpers ----------------------------------------------------
__device__ __forceinline__ uint32_t smem_u32(const void* p) {
    uint32_t a;
    asm("{ .reg .u64 t; cvta.to.shared.u64 t, %1; cvt.u32.u64 %0, t; }" : "=r"(a) : "l"(p));
    return a;
}
__device__ __forceinline__ void sts32(uint32_t addr, uint32_t v) {
    asm volatile("st.shared.b32 [%0], %1;" :: "r"(addr), "r"(v) : "memory");
}
__device__ __forceinline__ void ldsm4(uint32_t addr, uint32_t* r) {
    asm volatile("ldmatrix.sync.aligned.m8n8.x4.shared.b16 {%0,%1,%2,%3}, [%4];"
                 : "=r"(r[0]), "=r"(r[1]), "=r"(r[2]), "=r"(r[3]) : "r"(addr));
}
__device__ __forceinline__ void mma16816(float* c, const uint32_t* a, uint32_t b0, uint32_t b1) {
    asm volatile("mma.sync.aligned.m16n8k16.row.col.f32.bf16.bf16.f32 "
                 "{%0,%1,%2,%3}, {%4,%5,%6,%7}, {%8,%9}, {%0,%1,%2,%3};"
                 : "+f"(c[0]), "+f"(c[1]), "+f"(c[2]), "+f"(c[3])
                 : "r"(a[0]), "r"(a[1]), "r"(a[2]), "r"(a[3]), "r"(b0), "r"(b1));
}
__device__ __forceinline__ float2 cmul(float2 a, float2 b) {
    return make_float2(a.x * b.x - a.y * b.y, a.x * b.y + a.y * b.x);
}
__device__ __forceinline__ int fpad(int i) { return i + (i >> 4); }

// ---------------- 4/8-point DFT in registers ---------------------------------
__device__ __forceinline__ void dft4(float2 a, float2 b, float2 c, float2 d,
                                     float sgn, float2* o) {
    float t0r = a.x + c.x, t0i = a.y + c.y;
    float t1r = a.x - c.x, t1i = a.y - c.y;
    float t2r = b.x + d.x, t2i = b.y + d.y;
    float t3r = -sgn * (b.y - d.y), t3i = sgn * (b.x - d.x);
    o[0] = make_float2(t0r + t2r, t0i + t2i);
    o[1] = make_float2(t1r + t3r, t1i + t3i);
    o[2] = make_float2(t0r - t2r, t0i - t2i);
    o[3] = make_float2(t1r - t3r, t1i - t3i);
}
__device__ __forceinline__ void dft8(float2* x, float sgn) {
    const float Rq = 0.7071067811865476f;
    float2 E[4], O[4];
    dft4(x[0], x[2], x[4], x[6], sgn, E);
    dft4(x[1], x[3], x[5], x[7], sgn, O);
    float2 w1 = make_float2(Rq, sgn * Rq);
    float2 w2 = make_float2(0.f, sgn);
    float2 w3 = make_float2(-Rq, sgn * Rq);
    O[1] = cmul(O[1], w1);
    O[2] = cmul(O[2], w2);
    O[3] = cmul(O[3], w3);
#pragma unroll
    for (int k = 0; k < 4; k++) {
        x[k]     = make_float2(E[k].x + O[k].x, E[k].y + O[k].y);
        x[k + 4] = make_float2(E[k].x - O[k].x, E[k].y - O[k].y);
    }
}

// apply stage twiddles W^p..W^7p (p = tid >> sh scaled) to both rows
__device__ __forceinline__ void twiddle_x2(float2* x, float2* y, int tid, int sh, float sgn) {
    int   p  = tid >> sh;
    float th = sgn * 0.0015339807878856412f * (float)(p << sh);  // 2π/4096
    float c1v, s1v;
    __sincosf(th, &s1v, &c1v);
    float2 W1 = make_float2(c1v, s1v);
    float2 W2 = cmul(W1, W1);
    float2 W3 = cmul(W2, W1);
    float2 W4 = cmul(W2, W2);
    float2 W5 = cmul(W3, W2);
    float2 W6 = cmul(W3, W3);
    float2 W7 = cmul(W4, W3);
    x[1] = cmul(x[1], W1); x[2] = cmul(x[2], W2); x[3] = cmul(x[3], W3);
    x[4] = cmul(x[4], W4); x[5] = cmul(x[5], W5); x[6] = cmul(x[6], W6);
    x[7] = cmul(x[7], W7);
    y[1] = cmul(y[1], W1); y[2] = cmul(y[2], W2); y[3] = cmul(y[3], W3);
    y[4] = cmul(y[4], W4); y[5] = cmul(y[5], W5); y[6] = cmul(y[6], W6);
    y[7] = cmul(y[7], W7);
}

// one generic smem->smem Stockham stage (both rows); t in [0,3]
__device__ __forceinline__ void fft_stage_smem(float2* A, float2* B, int tid,
                                               float sgn, int t) {
    int sh = 3 * t;
    int s  = 1 << sh;
    float2 x[8], y[8];
#pragma unroll
    for (int j = 0; j < 8; j++) {
        int ii = fpad(tid + (j << 9));
        x[j] = A[ii];
        y[j] = B[ii];
    }
    __syncthreads();
    dft8(x, sgn);
    dft8(y, sgn);
    if (t < 3) twiddle_x2(x, y, tid, sh, sgn);
    int q    = tid & (s - 1);
    int base = q + ((tid >> sh) << (sh + 3));
#pragma unroll
    for (int k = 0; k < 8; k++) {
        int oo = fpad(base + (k << sh));
        A[oo] = x[k];
        B[oo] = y[k];
    }
    __syncthreads();
}

#define ROW_PAD   4352                              // 4096 + 256 float2
#define FFT_SMEM2 (2 * ROW_PAD * (int)sizeof(float2))  // 69632 B
#define FFT_T     512

// ---------------- K1: forward rfft (ortho), 2 rows per CTA -------------------
__global__ void __launch_bounds__(FFT_T, 2) k_fwd(const float* __restrict__ xg) {
    extern __shared__ float2 smc[];
    float2* A = smc;
    float2* B = smc + ROW_PAD;
    int row0 = blockIdx.x * 2;
    int row1 = row0 + 1;
    int tid  = threadIdx.x;

    const float2* xin0 = (const float2*)(xg + (size_t)row0 * Ll);
    const float2* xin1 = (const float2*)(xg + (size_t)row1 * Ll);

    // stage 0: global -> registers -> smem (no staging pass)
    {
        float2 x[8], y[8];
#pragma unroll
        for (int j = 0; j < 8; j++) {
            int m = tid + (j << 9);
            x[j] = xin0[m];                  // (even, odd) packed complex
            y[j] = xin1[m];
        }
        dft8(x, -1.0f);
        dft8(y, -1.0f);
        twiddle_x2(x, y, tid, 0, -1.0f);
        int base = tid << 3;
#pragma unroll
        for (int k = 0; k < 8; k++) {
            int oo = fpad(base + k);
            A[oo] = x[k];
            B[oo] = y[k];
        }
        __syncthreads();
    }
    fft_stage_smem(A, B, tid, -1.0f, 1);
    fft_stage_smem(A, B, tid, -1.0f, 2);
    // stage 3: thread-local slots (read/write same indices), no twiddle
    {
        float2 x[8], y[8];
#pragma unroll
        for (int j = 0; j < 8; j++) {
            int ii = fpad(tid + (j << 9));
            x[j] = A[ii];
            y[j] = B[ii];
        }
        dft8(x, -1.0f);
        dft8(y, -1.0f);
#pragma unroll
        for (int k = 0; k < 8; k++) {
            int oo = fpad(tid + (k << 9));
            A[oo] = x[k];
            B[oo] = y[k];
        }
        __syncthreads();
    }

    // Hermitian unpack, paired: X[k] = E + U, X[N-k] = conj(E - U), U = W^k O
    const float sc = 0.011048543456039804f;  // 1/sqrt(8192)
    float* outre0 = g_fxre + (size_t)row0 * Ff;
    float* outim0 = g_fxim + (size_t)row0 * Ff;
    float* outre1 = g_fxre + (size_t)row1 * Ff;
    float* outim1 = g_fxim + (size_t)row1 * Ff;
#pragma unroll 1
    for (int i = 0; i < 4; i++) {
        int k = tid + (i << 9);              // [0, 2048)
        if (k == 0) {
#pragma unroll
            for (int r = 0; r < 2; r++) {
                float2* T   = r ? B : A;
                float*  ore = r ? outre1 : outre0;
                float*  oim = r ? outim1 : outim0;
                float2 z0 = T[fpad(0)];
                ore[0]    = (z0.x + z0.y) * sc;  oim[0]    = 0.f;
                ore[4096] = (z0.x - z0.y) * sc;  oim[4096] = 0.f;
                float2 zc = T[fpad(2048)];
                ore[2048] = zc.x * sc;           oim[2048] = -zc.y * sc;
            }
        } else {
            int   m = 4096 - k;
            int   pk = fpad(k), pm = fpad(m);
            float cw, sw;
            __sincosf((float)k * (3.14159265358979324f / 4096.0f), &sw, &cw);
#pragma unroll
            for (int r = 0; r < 2; r++) {
                float2* T   = r ? B : A;
                float*  ore = r ? outre1 : outre0;
                float*  oim = r ? outim1 : outim0;
                float2 zk = T[pk], zm = T[pm];
                float Er = 0.5f * (zk.x + zm.x), Ei = 0.5f * (zk.y - zm.y);
                float Or = 0.5f * (zk.y + zm.y), Oi = 0.5f * (zm.x - zk.x);
                float Ur = cw * Or + sw * Oi;
                float Ui = cw * Oi - sw * Or;
                ore[k] = (Er + Ur) * sc;  oim[k] = (Ei + Ui) * sc;
                ore[m] = (Er - Ur) * sc;  oim[m] = (Ui - Ei) * sc;
            }
        }
    }
}

// ---------------- K2a: conv1 via mma.sync bf16 + SELU + f-sum ----------------
#define A_TAP_BYTES 16384
#define B_BYTES     8448          // 66 * 128
__global__ void __launch_bounds__(256, 3) k_conv(const float* __restrict__ w1R,
                                                 const float* __restrict__ b1R,
                                                 const float* __restrict__ w1I,
                                                 const float* __restrict__ b1I) {
    extern __shared__ __align__(1024) char dynsm[];
    __shared__ float s_red[2][128];

    int seg  = blockIdx.x;
    int b    = blockIdx.y;
    int path = blockIdx.z;
    const float* in = (path == 0) ? g_fxre : g_fxim;
    const float* w1 = (path == 0) ? w1R : w1I;
    const float* b1 = (path == 0) ? b1R : b1I;

    int tid  = threadIdx.x;
    int wid  = tid >> 5;
    int lane = tid & 31;
    int wm   = wid & 3;            // M group (32 rows)
    int wn   = wid >> 2;           // N group (32 cols)

    int t_beg = seg * TPS;
    int t_end = t_beg + TPS;       // 13*5 = 65 exactly

    uint32_t A0 = smem_u32(dynsm);
    uint32_t B0 = A0 + 3 * A_TAP_BYTES;

    // ---- weights -> bf16 smem (one-time, float2 loads) ----
    for (int idx = tid; idx < 128 * 32; idx += 256) {
        int h  = idx >> 5;
        int cp = idx & 31;
        const float2* wp = (const float2*)(w1 + ((size_t)(h * 64 + 2 * cp)) * 3);
        float2 v01 = wp[0];
        float2 v23 = wp[1];
        float2 v45 = wp[2];
        uint32_t off = (uint32_t)h * 128 + (((uint32_t)cp * 4) ^ (((uint32_t)h & 7) << 4));
        __nv_bfloat162 t0 = __floats2bfloat162_rn(v01.x, v23.y);
        __nv_bfloat162 t1 = __floats2bfloat162_rn(v01.y, v45.x);
        __nv_bfloat162 t2 = __floats2bfloat162_rn(v23.x, v45.y);
        sts32(A0 + 0 * A_TAP_BYTES + off, *(uint32_t*)&t0);
        sts32(A0 + 1 * A_TAP_BYTES + off, *(uint32_t*)&t1);
        sts32(A0 + 2 * A_TAP_BYTES + off, *(uint32_t*)&t2);
    }

    float bias[2][2];
#pragma unroll
    for (int mi = 0; mi < 2; mi++)
#pragma unroll
        for (int hf = 0; hf < 2; hf++)
            bias[mi][hf] = b1[wm * 32 + mi * 16 + (lane >> 2) + hf * 8];

    // B loader: thread -> (cp = tid>>3, jslot = tid&7), 9 j-iterations
    int cp = tid >> 3;
    int js = tid & 7;
    const float* r0g = in + (size_t)(b * 64 + 2 * cp) * Ff;
    const float* r1g = r0g + Ff;
    uint32_t brot = ((uint32_t)js << 4);

    uint32_t xv[9];
    auto fetchB = [&](int t) {
        int f0 = t * TILE_F;
#pragma unroll
        for (int i = 0; i < 9; i++) {
            int j = js + 8 * i;
            float v0 = 0.f, v1 = 0.f;
            if (j < 66) {
                int f = f0 - 1 + j;
                if (f >= 0 && f <= 4096) { v0 = r0g[f]; v1 = r1g[f]; }
            }
            __nv_bfloat162 tv = __floats2bfloat162_rn(v0, v1);
            xv[i] = *(uint32_t*)&tv;
        }
    };
    auto storeB = [&](uint32_t Bbuf) {
#pragma unroll
        for (int i = 0; i < 9; i++) {
            int j = js + 8 * i;
            if (j < 66)
                sts32(Bbuf + (uint32_t)j * 128 + (((uint32_t)cp * 4) ^ brot), xv[i]);
        }
    };

    float s[2][2] = {{0.f, 0.f}, {0.f, 0.f}};
    const float SC = 1.0507009873554805f;
    const float SA = 1.7580993408473766f;    // SC * AL

    // lane pieces for ldmatrix addressing
    uint32_t lrow_off = (uint32_t)((lane & 7) + (lane & 8));      // A frag rows
    uint32_t kbyte_hi = (lane & 16) ? 16u : 0u;                   // A k-half
    uint32_t b_row_l  = (uint32_t)(wn * 32 + (lane & 7) + ((lane & 16) ? 8 : 0)); // B rows
    uint32_t b_khalf  = (lane & 8) ? 16u : 0u;                    // B k-half

    fetchB(t_beg);
    storeB(B0 + (uint32_t)(t_beg & 1) * B_BYTES);
    __syncthreads();

#pragma unroll 1
    for (int t = t_beg; t < t_end; t++) {
        if (t + 1 < t_end) fetchB(t + 1);    // prefetch into regs

        uint32_t Bbuf = B0 + (uint32_t)(t & 1) * B_BYTES;
        float acc[2][4][4];
#pragma unroll
        for (int mi = 0; mi < 2; mi++)
#pragma unroll
            for (int ni = 0; ni < 4; ni++)
#pragma unroll
                for (int e = 0; e < 4; e++) acc[mi][ni][e] = 0.f;

#pragma unroll
        for (int tap = 0; tap < 3; tap++) {
            uint32_t Atap = A0 + (uint32_t)tap * A_TAP_BYTES;
#pragma unroll
            for (int kf = 0; kf < 4; kf++) {
                uint32_t a[2][4];
#pragma unroll
                for (int mi = 0; mi < 2; mi++) {
                    uint32_t row  = (uint32_t)(wm * 32 + mi * 16) + lrow_off;
                    uint32_t kb   = (uint32_t)kf * 32 + kbyte_hi;
                    uint32_t addr = Atap + row * 128 + (kb ^ ((row & 7) << 4));
                    ldsm4(addr, a[mi]);
                }
                uint32_t bb[4][2];
                uint32_t kbB = (uint32_t)kf * 32 + b_khalf;
#pragma unroll
                for (int np = 0; np < 2; np++) {
                    uint32_t r    = b_row_l + (uint32_t)(np * 16 + tap);
                    uint32_t addr = Bbuf + r * 128 + (kbB ^ ((r & 7) << 4));
                    uint32_t rg[4];
                    ldsm4(addr, rg);
                    bb[np * 2][0]     = rg[0];
                    bb[np * 2][1]     = rg[1];
                    bb[np * 2 + 1][0] = rg[2];
                    bb[np * 2 + 1][1] = rg[3];
                }
#pragma unroll
                for (int mi = 0; mi < 2; mi++)
#pragma unroll
                    for (int ni = 0; ni < 4; ni++)
                        mma16816(acc[mi][ni], a[mi], bb[ni][0], bb[ni][1]);
            }
        }

        // epilogue: bias + SELU + row sums (+ edges only in boundary tiles)
        if (t != 0 && t != NTILES - 1) {
#pragma unroll
            for (int mi = 0; mi < 2; mi++)
#pragma unroll
                for (int ni = 0; ni < 4; ni++)
#pragma unroll
                    for (int e = 0; e < 4; e++) {
                        int   hf = e >> 1;
                        float v  = acc[mi][ni][e] + bias[mi][hf];
                        float y  = (v > 0.f) ? SC * v : SA * (__expf(v) - 1.f);
                        s[mi][hf] += y;
                    }
        } else {
            int f0 = t * TILE_F;
#pragma unroll
            for (int mi = 0; mi < 2; mi++)
#pragma unroll
                for (int ni = 0; ni < 4; ni++)
#pragma unroll
                    for (int e = 0; e < 4; e++) {
                        int f = f0 + wn * 32 + ni * 8 + (lane & 3) * 2 + (e & 1);
                        if (f <= 4096) {
                            int   hf = e >> 1;
                            float v  = acc[mi][ni][e] + bias[mi][hf];
                            float y  = (v > 0.f) ? SC * v : SA * (__expf(v) - 1.f);
                            s[mi][hf] += y;
                            if (f == 0 || f == 4096) {
                                int    h  = wm * 32 + mi * 16 + (lane >> 2) + hf * 8;
                                size_t eb = (((size_t)path * 64 + b) * 128 + h) * 2;
                                g_edge[eb + ((f == 0) ? 0 : 1)] = y;
                            }
                        }
                    }
        }

        if (t + 1 < t_end) storeB(B0 + (uint32_t)((t + 1) & 1) * B_BYTES);
        __syncthreads();
    }

    // cross-lane reduce (cols live on lane%4 quads)
#pragma unroll
    for (int mi = 0; mi < 2; mi++)
#pragma unroll
        for (int hf = 0; hf < 2; hf++) {
            float v = s[mi][hf];
            v += __shfl_xor_sync(0xffffffffu, v, 1);
            v += __shfl_xor_sync(0xffffffffu, v, 2);
            s[mi][hf] = v;
        }
    if ((lane & 3) == 0) {
#pragma unroll
        for (int mi = 0; mi < 2; mi++)
#pragma unroll
            for (int hf = 0; hf < 2; hf++) {
                int h = wm * 32 + mi * 16 + (lane >> 2) + hf * 8;
                s_red[wn][h] = s[mi][hf];
            }
    }
    __syncthreads();
    if (tid < 128) {
        float S = s_red[0][tid] + s_red[1][tid];
        g_Spart[(((size_t)seg * 2 + path) * 64 + b) * 128 + tid] = S;
    }
}

// ---------------- K2b: pooled conv2 + softmax --------------------------------
__global__ void __launch_bounds__(128) k_pool(const float* __restrict__ w2R,
                                              const float* __restrict__ b2R,
                                              const float* __restrict__ w2I,
                                              const float* __restrict__ b2I) {
    int bx   = blockIdx.x;
    int path = bx >> 6;
    int b    = bx & 63;
    const float* w2 = path ? w2I : w2R;
    const float* b2 = path ? b2I : b2R;
    int h = threadIdx.x;

    size_t base = ((size_t)path * 64 + b) * 128 + h;
    float  S    = 0.f;
#pragma unroll
    for (int sg = 0; sg < SEG; sg++)
        S += g_Spart[(((size_t)sg * 2 + path) * 64 + b) * 128 + h];
    float y0 = g_edge[base * 2 + 0];
    float yl = g_edge[base * 2 + 1];

    __shared__ float red[3][128];
#pragma unroll
    for (int n = 0; n < 3; n++) {
        const float* wp = w2 + ((size_t)n * 128 + h) * 3;
        red[n][h] = wp[0] * (S - yl) + wp[1] * S + wp[2] * (S - y0);
    }
    __syncthreads();
    for (int off = 64; off >= 1; off >>= 1) {
        if (h < off) {
#pragma unroll
            for (int n = 0; n < 3; n++) red[n][h] += red[n][h + off];
        }
        __syncthreads();
    }
    if (h == 0) {
        float z0 = red[0][0] / (float)Ff + b2[0];
        float z1 = red[1][0] / (float)Ff + b2[1];
        float z2 = red[2][0] / (float)Ff + b2[2];
        float m  = fmaxf(z0, fmaxf(z1, z2));
        float e0 = expf(z0 - m), e1 = expf(z1 - m), e2 = expf(z2 - m);
        float inv = 1.f / (e0 + e1 + e2);
        size_t cb = ((size_t)path * 64 + b) * 3;
        g_C[cb + 0] = e0 * inv;
        g_C[cb + 1] = e1 * inv;
        g_C[cb + 2] = e2 * inv;
    }
}

// ---------------- K3: fused Kf-multiply + inverse pack + irfft ---------------
// Rows paired across BATCH (same channel c): row0 = (2bp)*64+c, row1 = row0+64.
// Both rows share the same param channel -> param loads serve both rows.
__global__ void __launch_bounds__(FFT_T, 2) k_inv(const float* __restrict__ param,
                                                  float* __restrict__ out) {
    extern __shared__ float2 smc[];
    float2* A = smc;
    float2* B = smc + ROW_PAD;

    int bp   = blockIdx.x >> 6;              // batch pair
    int c    = blockIdx.x & 63;              // shared channel
    int b0   = 2 * bp;
    int b1   = b0 + 1;
    int row0 = b0 * 64 + c;
    int row1 = b1 * 64 + c;
    int tid  = threadIdx.x;

    // per-row coefficients
    float cr0a = g_C[((size_t)0 * 64 + b0) * 3 + 0];
    float cr1a = g_C[((size_t)0 * 64 + b0) * 3 + 1];
    float cr2a = g_C[((size_t)0 * 64 + b0) * 3 + 2];
    float ci0a = g_C[((size_t)1 * 64 + b0) * 3 + 0];
    float ci1a = g_C[((size_t)1 * 64 + b0) * 3 + 1];
    float ci2a = g_C[((size_t)1 * 64 + b0) * 3 + 2];
    float cr0b = g_C[((size_t)0 * 64 + b1) * 3 + 0];
    float cr1b = g_C[((size_t)0 * 64 + b1) * 3 + 1];
    float cr2b = g_C[((size_t)0 * 64 + b1) * 3 + 2];
    float ci0b = g_C[((size_t)1 * 64 + b1) * 3 + 0];
    float ci1b = g_C[((size_t)1 * 64 + b1) * 3 + 1];
    float ci2b = g_C[((size_t)1 * 64 + b1) * 3 + 2];

    const float* fre0 = g_fxre + (size_t)row0 * Ff;
    const float* fim0 = g_fxim + (size_t)row0 * Ff;
    const float* fre1 = g_fxre + (size_t)row1 * Ff;
    const float* fim1 = g_fxim + (size_t)row1 * Ff;

    // load param once per bin; produce Y for BOTH rows
    auto specmul2 = [&](int f, float2& Ya, float2& Yb) {
        float2 w0 = *(const float2*)(param + (((size_t)0 * 64 + c) * Ff + f) * 2);
        float2 w1 = *(const float2*)(param + (((size_t)1 * 64 + c) * Ff + f) * 2);
        float2 w2 = *(const float2*)(param + (((size_t)2 * 64 + c) * Ff + f) * 2);
        float KfRa = cr0a * w0.x + cr1a * w1.x + cr2a * w2.x;
        float KfIa = ci0a * w0.y + ci1a * w1.y + ci2a * w2.y;
        float KfRb = cr0b * w0.x + cr1b * w1.x + cr2b * w2.x;
        float KfIb = ci0b * w0.y + ci1b * w1.y + ci2b * w2.y;
        float fra = fre0[f], fia = fim0[f];
        float frb = fre1[f], fib = fim1[f];
        Ya = make_float2(fra * KfRa - fia * KfIa, fra * KfIa + fia * KfRa);
        Yb = make_float2(frb * KfRb - fib * KfIb, frb * KfIb + fib * KfRb);
    };

    // fused: Y = fx*Kf and inverse pack Z[k] = E + iO, written to smem once
#pragma unroll 1
    for (int i = 0; i < 4; i++) {
        int k = tid + (i << 9);              // [0, 2048)
        if (k == 0) {
            float2 Y0a, Y0b, Yna, Ynb, Yca, Ycb;
            specmul2(0, Y0a, Y0b);           // imag discarded (C2R)
            specmul2(4096, Yna, Ynb);        // Nyquist, imag discarded
            specmul2(2048, Yca, Ycb);        // self-paired bin
            A[fpad(0)] = make_float2(0.5f * (Y0a.x + Yna.x), 0.5f * (Y0a.x - Yna.x));
            B[fpad(0)] = make_float2(0.5f * (Y0b.x + Ynb.x), 0.5f * (Y0b.x - Ynb.x));
            A[fpad(2048)] = make_float2(Yca.x, -Yca.y);
            B[fpad(2048)] = make_float2(Ycb.x, -Ycb.y);
        } else {
            int   m  = 4096 - k;
            int   pk = fpad(k), pm = fpad(m);
            float cw, sw;
            __sincosf((float)k * (3.14159265358979324f / 4096.0f), &sw, &cw);
            float2 Yka, Ykb, Yma, Ymb;
            specmul2(k, Yka, Ykb);
            specmul2(m, Yma, Ymb);
            {
                float Er = 0.5f * (Yka.x + Yma.x), Ei = 0.5f * (Yka.y - Yma.y);
                float Dr = 0.5f * (Yka.x - Yma.x), Di = 0.5f * (Yka.y + Yma.y);
                float Or = Dr * cw - Di * sw;
                float Oi = Dr * sw + Di * cw;
                A[pk] = make_float2(Er - Oi, Ei + Or);
                A[pm] = make_float2(Er + Oi, Or - Ei);
            }
            {
                float Er = 0.5f * (Ykb.x + Ymb.x), Ei = 0.5f * (Ykb.y - Ymb.y);
                float Dr = 0.5f * (Ykb.x - Ymb.x), Di = 0.5f * (Ykb.y + Ymb.y);
                float Or = Dr * cw - Di * sw;
                float Oi = Dr * sw + Di * cw;
                B[pk] = make_float2(Er - Oi, Ei + Or);
                B[pm] = make_float2(Er + Oi, Or - Ei);
            }
        }
    }
    __syncthreads();

    fft_stage_smem(A, B, tid, +1.0f, 0);
    fft_stage_smem(A, B, tid, +1.0f, 1);
    fft_stage_smem(A, B, tid, +1.0f, 2);

    // stage 3: butterfly in registers, scaled write DIRECTLY to global
    const float sc = 0.022097086912079608f;  // sqrt(8192) / 4096
    float2* o0 = (float2*)(out + (size_t)row0 * Ll);
    float2* o1 = (float2*)(out + (size_t)row1 * Ll);
    {
        float2 x[8], y[8];
#pragma unroll
        for (int j = 0; j < 8; j++) {
            int ii = fpad(tid + (j << 9));
            x[j] = A[ii];
            y[j] = B[ii];
        }
        dft8(x, +1.0f);
        dft8(y, +1.0f);
#pragma unroll
        for (int k = 0; k < 8; k++) {
            int m = tid + (k << 9);
            o0[m] = make_float2(x[k].x * sc, x[k].y * sc);
            o1[m] = make_float2(y[k].x * sc, y[k].y * sc);
        }
    }
}

// ---------------- launch -----------------------------------------------------
extern "C" void kernel_launch(void* const* d_in, const int* in_sizes, int n_in,
                              void* d_out, int out_size) {
    const float* x   = (const float*)d_in[0];
    const float* par = (const float*)d_in[1];
    const float* wR1 = (const float*)d_in[2];
    const float* bR1 = (const float*)d_in[3];
    const float* wR2 = (const float*)d_in[4];
    const float* bR2 = (const float*)d_in[5];
    const float* wI1 = (const float*)d_in[6];
    const float* bI1 = (const float*)d_in[7];
    const float* wI2 = (const float*)d_in[8];
    const float* bI2 = (const float*)d_in[9];
    float* out = (float*)d_out;

    const int convSmem = 3 * A_TAP_BYTES + 2 * B_BYTES;  // 66048
    cudaFuncSetAttribute(k_conv, cudaFuncAttributeMaxDynamicSharedMemorySize, convSmem);
    cudaFuncSetAttribute(k_fwd,  cudaFuncAttributeMaxDynamicSharedMemorySize, FFT_SMEM2);
    cudaFuncSetAttribute(k_inv,  cudaFuncAttributeMaxDynamicSharedMemorySize, FFT_SMEM2);

    k_fwd<<<Bb * Cc / 2, FFT_T, FFT_SMEM2>>>(x);
    dim3 gconv(SEG, Bb, 2);
    k_conv<<<gconv, 256, convSmem>>>(wR1, bR1, wI1, bI1);
    k_pool<<<2 * Bb, 128>>>(wR2, bR2, wI2, bI2);
    k_inv<<<Bb * Cc / 2, FFT_T, FFT_SMEM2>>>(par, out);
}